// round 1
// baseline (speedup 1.0000x reference)
#include <cuda_runtime.h>
#include <cstddef>

#define B_      128
#define NNZ_    128
#define H_      128
#define KOUT_   4096
#define FDIM_   135909

// Intermediate val1 [B, H] — device global scratch (no allocations allowed).
__device__ float g_val1[B_ * H_];

// ---------------------------------------------------------------------------
// Layer 1: val1[b,h] = relu( sum_i v[b,i] * W1[h, fidx[b,i]] + b1[h] )
// One block per batch row b, 128 threads = one per hidden unit h.
// W1 is [H, FDIM] row-major, so the gather of column f across h is inherently
// uncoalesced (stride FDIM). We preload indices/values to smem and unroll the
// i-loop by 16 to keep 16 independent DRAM loads in flight per thread.
// ---------------------------------------------------------------------------
__global__ __launch_bounds__(128) void layer1_kernel(
    const float* __restrict__ inv,
    const int*   __restrict__ fidx,
    const float* __restrict__ W1,
    const float* __restrict__ b1)
{
    const int b = blockIdx.x;
    const int h = threadIdx.x;

    __shared__ int   sidx[NNZ_];
    __shared__ float sval[NNZ_];
    sidx[h] = fidx[(b << 7) + h];
    sval[h] = inv[(b << 7) + h];
    __syncthreads();

    const float* w = W1 + (size_t)h * FDIM_;
    float acc = b1[h];

    #pragma unroll
    for (int i0 = 0; i0 < NNZ_; i0 += 16) {
        float wv[16];
        #pragma unroll
        for (int j = 0; j < 16; j++) wv[j] = __ldg(w + sidx[i0 + j]);
        #pragma unroll
        for (int j = 0; j < 16; j++) acc = fmaf(sval[i0 + j], wv[j], acc);
    }

    g_val1[(b << 7) + h] = fmaxf(acc, 0.0f);
}

// ---------------------------------------------------------------------------
// Layer 2: val2[b,k] = <val1[b,:], W2[lab[b,k],:]> + b2[lab[b,k]]
// W2 row = 128 floats = 512B contiguous: one warp reads a row as 32 x float4
// (perfectly coalesced, 4 x 128B lines). Each warp handles 4 outputs so 4
// independent row-loads are in flight (MLP=4). Block = 256 thr = 8 warps =
// 32 outputs, all for the same batch row b -> val1[b] staged once in smem.
// Grid: (B*KOUT)/32 = 16384 blocks.
// ---------------------------------------------------------------------------
__global__ __launch_bounds__(256) void layer2_kernel(
    const int*   __restrict__ lab,
    const float* __restrict__ W2,
    const float* __restrict__ b2,
    float*       __restrict__ out,
    float*       __restrict__ out_lab)   // may be null
{
    const int warp = threadIdx.x >> 5;
    const int lane = threadIdx.x & 31;
    const int b     = blockIdx.x >> 7;                      // 128 blocks per b
    const int kbase = ((blockIdx.x & 127) << 5) + (warp << 2);

    __shared__ float4 s4[32];
    if (threadIdx.x < 32)
        s4[threadIdx.x] = reinterpret_cast<const float4*>(g_val1 + (b << 7))[threadIdx.x];
    __syncthreads();

    const float4 sv = s4[lane];
    const int base = (b << 12) + kbase;

    int rows[4];
    #pragma unroll
    for (int j = 0; j < 4; j++) rows[j] = lab[base + j];

    float acc[4];
    #pragma unroll
    for (int j = 0; j < 4; j++) {
        const float4 wv = __ldg(reinterpret_cast<const float4*>(W2) +
                                ((size_t)rows[j] << 5) + lane);
        acc[j] = wv.x * sv.x + wv.y * sv.y + wv.z * sv.z + wv.w * sv.w;
    }

    #pragma unroll
    for (int j = 0; j < 4; j++) {
        #pragma unroll
        for (int o = 16; o > 0; o >>= 1)
            acc[j] += __shfl_xor_sync(0xffffffffu, acc[j], o);
    }

    if (lane < 4) {
        const int j = lane;
        const int r = rows[j];
        out[base + j] = acc[j] + __ldg(b2 + r);
        if (out_lab) out_lab[base + j] = (float)r;
    }
}

// ---------------------------------------------------------------------------
extern "C" void kernel_launch(void* const* d_in, const int* in_sizes, int n_in,
                              void* d_out, int out_size)
{
    const float* inv  = (const float*)d_in[0];   // in_values        [B, NNZ]
    const int*   fidx = (const int*)  d_in[1];   // active_in_indices[B, NNZ]
    const int*   lab  = (const int*)  d_in[2];   // active_label_idx [B, KOUT]
    const float* W1   = (const float*)d_in[3];   // [H, FDIM]
    const float* b1   = (const float*)d_in[4];   // [H]
    const float* W2   = (const float*)d_in[5];   // [C, H]
    const float* b2   = (const float*)d_in[6];   // [C]

    float* out = (float*)d_out;
    const int n_val2 = B_ * KOUT_;
    float* out_lab = (out_size >= 2 * n_val2) ? (out + n_val2) : nullptr;

    layer1_kernel<<<B_, 128>>>(inv, fidx, W1, b1);
    layer2_kernel<<<(B_ * KOUT_) / 32, 256>>>(lab, W2, b2, out, out_lab);
}

// round 2
// speedup vs baseline: 1.0304x; 1.0304x over previous
#include <cuda_runtime.h>
#include <cstddef>

#define B_      128
#define NNZ_    128
#define H_      128
#define KOUT_   4096
#define FDIM_   135909

// Intermediate val1 [B, H] — device global scratch (no allocations allowed).
__device__ float g_val1[B_ * H_];

// ---------------------------------------------------------------------------
// Layer 1: val1[b,h] = relu( sum_i v[b,i] * W1[h, fidx[b,i]] + b1[h] )
// One block per batch row b, 128 threads = one per hidden unit h.
// W1 is [H, FDIM] row-major, so the gather of column f across h is inherently
// uncoalesced (stride FDIM). We preload indices/values to smem and unroll the
// i-loop by 16 to keep 16 independent DRAM loads in flight per thread.
// ---------------------------------------------------------------------------
__global__ __launch_bounds__(128) void layer1_kernel(
    const float* __restrict__ inv,
    const int*   __restrict__ fidx,
    const float* __restrict__ W1,
    const float* __restrict__ b1)
{
    const int b = blockIdx.x;
    const int h = threadIdx.x;

    __shared__ int   sidx[NNZ_];
    __shared__ float sval[NNZ_];
    sidx[h] = fidx[(b << 7) + h];
    sval[h] = inv[(b << 7) + h];
    __syncthreads();

    const float* w = W1 + (size_t)h * FDIM_;
    float acc = b1[h];

    #pragma unroll
    for (int i0 = 0; i0 < NNZ_; i0 += 16) {
        float wv[16];
        #pragma unroll
        for (int j = 0; j < 16; j++) wv[j] = __ldg(w + sidx[i0 + j]);
        #pragma unroll
        for (int j = 0; j < 16; j++) acc = fmaf(sval[i0 + j], wv[j], acc);
    }

    g_val1[(b << 7) + h] = fmaxf(acc, 0.0f);
}

// ---------------------------------------------------------------------------
// Layer 2: val2[b,k] = <val1[b,:], W2[lab[b,k],:]> + b2[lab[b,k]]
// W2 row = 128 floats = 512B contiguous: one warp reads a row as 32 x float4
// (perfectly coalesced, 4 x 128B lines). Each warp handles 4 outputs so 4
// independent row-loads are in flight (MLP=4). Block = 256 thr = 8 warps =
// 32 outputs, all for the same batch row b -> val1[b] staged once in smem.
// Grid: (B*KOUT)/32 = 16384 blocks.
// ---------------------------------------------------------------------------
__global__ __launch_bounds__(256) void layer2_kernel(
    const int*   __restrict__ lab,
    const float* __restrict__ W2,
    const float* __restrict__ b2,
    float*       __restrict__ out,
    float*       __restrict__ out_lab)   // may be null
{
    const int warp = threadIdx.x >> 5;
    const int lane = threadIdx.x & 31;
    const int b     = blockIdx.x >> 7;                      // 128 blocks per b
    const int kbase = ((blockIdx.x & 127) << 5) + (warp << 2);

    __shared__ float4 s4[32];
    if (threadIdx.x < 32)
        s4[threadIdx.x] = reinterpret_cast<const float4*>(g_val1 + (b << 7))[threadIdx.x];
    __syncthreads();

    const float4 sv = s4[lane];
    const int base = (b << 12) + kbase;

    int rows[4];
    #pragma unroll
    for (int j = 0; j < 4; j++) rows[j] = lab[base + j];

    float acc[4];
    #pragma unroll
    for (int j = 0; j < 4; j++) {
        const float4 wv = __ldg(reinterpret_cast<const float4*>(W2) +
                                ((size_t)rows[j] << 5) + lane);
        acc[j] = wv.x * sv.x + wv.y * sv.y + wv.z * sv.z + wv.w * sv.w;
    }

    #pragma unroll
    for (int j = 0; j < 4; j++) {
        #pragma unroll
        for (int o = 16; o > 0; o >>= 1)
            acc[j] += __shfl_xor_sync(0xffffffffu, acc[j], o);
    }

    if (lane < 4) {
        const int j = lane;
        const int r = rows[j];
        out[base + j] = acc[j] + __ldg(b2 + r);
        if (out_lab) out_lab[base + j] = (float)r;
    }
}

// ---------------------------------------------------------------------------
extern "C" void kernel_launch(void* const* d_in, const int* in_sizes, int n_in,
                              void* d_out, int out_size)
{
    const float* inv  = (const float*)d_in[0];   // in_values        [B, NNZ]
    const int*   fidx = (const int*)  d_in[1];   // active_in_indices[B, NNZ]
    const int*   lab  = (const int*)  d_in[2];   // active_label_idx [B, KOUT]
    const float* W1   = (const float*)d_in[3];   // [H, FDIM]
    const float* b1   = (const float*)d_in[4];   // [H]
    const float* W2   = (const float*)d_in[5];   // [C, H]
    const float* b2   = (const float*)d_in[6];   // [C]

    float* out = (float*)d_out;
    const int n_val2 = B_ * KOUT_;
    float* out_lab = (out_size >= 2 * n_val2) ? (out + n_val2) : nullptr;

    layer1_kernel<<<B_, 128>>>(inv, fidx, W1, b1);
    layer2_kernel<<<(B_ * KOUT_) / 32, 256>>>(lab, W2, b2, out, out_lab);
}